// round 1
// baseline (speedup 1.0000x reference)
#include <cuda_runtime.h>
#include <math.h>

#define T_DIM 2048
#define B_DIM 4
#define E_DIM 512
#define H_DIM 8
#define HD    64
#define BH    (B_DIM*H_DIM)          // 32
#define SCALE 0.125f
#define M_ROWS (T_DIM*B_DIM)         // 8192
#define ATTN_ELEMS (T_DIM*B_DIM*E_DIM)  // 4194304

// ---------------- scratch (allocation-free rule: __device__ globals) ----------------
__device__ float g_q[BH * T_DIM * HD];     // [bh][t][d], pre-scaled by SCALE
__device__ float g_k[BH * T_DIM * HD];
__device__ float g_v[BH * T_DIM * HD];
__device__ float g_ctx[M_ROWS * E_DIM];    // attention output in [t*B+b][e] layout
__device__ float g_m[BH * T_DIM];          // row max
__device__ float g_il[BH * T_DIM];         // 1 / row sumexp

// fast exp on the FMA pipe (avoids the MUFU EX2 throughput wall: 268M exps total)
__device__ __forceinline__ float fexp(float x) {
    float t = x * 1.4426950408889634f;
    t = fmaxf(t, -126.0f);
    float fl = floorf(t);
    float f  = t - fl;                    // [0,1)
    float p  = 1.5403530e-4f;             // Taylor of 2^f, 7 terms
    p = fmaf(p, f, 1.3333558e-3f);
    p = fmaf(p, f, 9.6181291e-3f);
    p = fmaf(p, f, 5.5504109e-2f);
    p = fmaf(p, f, 2.4022651e-1f);
    p = fmaf(p, f, 6.9314718e-1f);
    p = fmaf(p, f, 1.0f);                 // [1,2)
    return __int_as_float(__float_as_int(p) + (((int)fl) << 23));
}

// ---------------- generic NT SGEMM: C[i][j] = sum_k A[i,k]*B[j,k] + bias[j] ----------
// mode 0: QKV epilogue (scatter to g_q/g_k/g_v, scale q)
// mode 1: out-projection (A is ignored; reads g_ctx), writes C[i*N+j]
__global__ void sgemm_nt(const float* __restrict__ A, const float* __restrict__ Bm,
                         const float* __restrict__ bias, float* __restrict__ C,
                         int N, int K, int mode)
{
    __shared__ float As[16][64];
    __shared__ float Bs[16][64];
    const int tid = threadIdx.x;
    const int n0 = blockIdx.x * 64;
    const int m0 = blockIdx.y * 64;
    const int r  = tid >> 2;     // 0..63
    const int c  = tid & 3;      // 0..3
    const int tx = tid & 15;
    const int ty = tid >> 4;

    const float* Ause = (mode == 1) ? g_ctx : A;
    const float* Aptr = Ause + (size_t)(m0 + r) * K + c * 4;
    const float* Bptr = Bm   + (size_t)(n0 + r) * K + c * 4;

    float acc[4][4] = {};
    for (int k0 = 0; k0 < K; k0 += 16) {
        float4 av = *(const float4*)(Aptr + k0);
        float4 bv = *(const float4*)(Bptr + k0);
        __syncthreads();
        As[c*4+0][r] = av.x; As[c*4+1][r] = av.y; As[c*4+2][r] = av.z; As[c*4+3][r] = av.w;
        Bs[c*4+0][r] = bv.x; Bs[c*4+1][r] = bv.y; Bs[c*4+2][r] = bv.z; Bs[c*4+3][r] = bv.w;
        __syncthreads();
        #pragma unroll
        for (int kk = 0; kk < 16; kk++) {
            float4 a4 = *(const float4*)&As[kk][ty*4];
            float4 b4 = *(const float4*)&Bs[kk][tx*4];
            float a[4] = {a4.x, a4.y, a4.z, a4.w};
            float b[4] = {b4.x, b4.y, b4.z, b4.w};
            #pragma unroll
            for (int i = 0; i < 4; i++)
                #pragma unroll
                for (int j = 0; j < 4; j++)
                    acc[i][j] = fmaf(a[i], b[j], acc[i][j]);
        }
    }

    #pragma unroll
    for (int ii = 0; ii < 4; ii++) {
        #pragma unroll
        for (int jj = 0; jj < 4; jj++) {
            int i = m0 + ty*4 + ii;
            int j = n0 + tx*4 + jj;
            float v = acc[ii][jj] + bias[j];
            if (mode == 0) {
                int t = i >> 2, b = i & 3;           // row of x is t*B + b
                int sect = j >> 9;                   // 0:q 1:k 2:v
                int jm = j & 511;
                int h = jm >> 6, d = jm & 63;
                int dst = (((b * H_DIM + h) * T_DIM) + t) * HD + d;
                if (sect == 0)      g_q[dst] = v * SCALE;
                else if (sect == 1) g_k[dst] = v;
                else                g_v[dst] = v;
            } else {
                C[(size_t)i * N + j] = v;
            }
        }
    }
}

// ---------------- flash attention per (bh, 64-row q tile) ----------------
#define FLASH_SMEM_FLOATS (3*4096 + 64*68 + 3*64)
__global__ void flash_kernel()
{
    extern __shared__ float sm[];
    float* Qt   = sm;              // [d][i]  64x64, d-major
    float* Kt   = Qt + 4096;       // [d][j]  64x64, d-major
    float* Vs   = Kt + 4096;       // [k][d]  64x64, natural
    float* Ss   = Vs + 4096;       // [i][j]  64x68 (padded)
    float* sm_m = Ss + 64*68;
    float* sm_l = sm_m + 64;
    float* sm_f = sm_l + 64;

    const int tid = threadIdx.x;
    const int bh  = blockIdx.y;
    const int q0  = blockIdx.x * 64;
    const int tx  = tid & 15, ty = tid >> 4;
    const int lr  = tid >> 2;      // load row 0..63
    const int lc  = tid & 3;       // 0..3

    const float* Qg = g_q + ((size_t)bh * T_DIM + q0) * HD;
    const float* Kg = g_k + (size_t)bh * T_DIM * HD;
    const float* Vg = g_v + (size_t)bh * T_DIM * HD;

    // load Q, transposed to d-major
    #pragma unroll
    for (int it = 0; it < 4; it++) {
        int d4 = lc * 4 + it;
        float4 qv = *(const float4*)(Qg + lr * HD + d4 * 4);
        Qt[(d4*4+0)*64 + lr] = qv.x;
        Qt[(d4*4+1)*64 + lr] = qv.y;
        Qt[(d4*4+2)*64 + lr] = qv.z;
        Qt[(d4*4+3)*64 + lr] = qv.w;
    }
    if (tid < 64) { sm_m[tid] = -1e30f; sm_l[tid] = 0.0f; }

    float o[4][4] = {};

    for (int k0 = 0; k0 < T_DIM; k0 += 64) {
        __syncthreads();   // prior P@V done; also covers Q load on first iter
        #pragma unroll
        for (int it = 0; it < 4; it++) {
            int d4 = lc * 4 + it;
            float4 kv = *(const float4*)(Kg + (size_t)(k0 + lr) * HD + d4 * 4);
            Kt[(d4*4+0)*64 + lr] = kv.x;
            Kt[(d4*4+1)*64 + lr] = kv.y;
            Kt[(d4*4+2)*64 + lr] = kv.z;
            Kt[(d4*4+3)*64 + lr] = kv.w;
            float4 vv = *(const float4*)(Vg + (size_t)(k0 + lr) * HD + d4 * 4);
            *(float4*)(Vs + lr * 64 + d4 * 4) = vv;
        }
        __syncthreads();

        // S = Q K^T (tile 64x64), 4x4 per thread
        float s[4][4] = {};
        #pragma unroll
        for (int d = 0; d < 64; d++) {
            float4 qa = *(const float4*)(Qt + d * 64 + ty * 4);
            float4 kb = *(const float4*)(Kt + d * 64 + tx * 4);
            float a[4] = {qa.x, qa.y, qa.z, qa.w};
            float b[4] = {kb.x, kb.y, kb.z, kb.w};
            #pragma unroll
            for (int i = 0; i < 4; i++)
                #pragma unroll
                for (int j = 0; j < 4; j++)
                    s[i][j] = fmaf(a[i], b[j], s[i][j]);
        }
        #pragma unroll
        for (int ii = 0; ii < 4; ii++)
            *(float4*)(Ss + (ty*4+ii)*68 + tx*4) =
                make_float4(s[ii][0], s[ii][1], s[ii][2], s[ii][3]);
        __syncthreads();

        // online softmax row update: 4 threads per row
        {
            const int row = tid >> 2, g = tid & 3;
            float* srow = Ss + row * 68;
            float mold = sm_m[row];
            float mx = mold;
            #pragma unroll
            for (int u = 0; u < 16; u++) mx = fmaxf(mx, srow[g + u*4]);
            mx = fmaxf(mx, __shfl_xor_sync(0xffffffffu, mx, 1));
            mx = fmaxf(mx, __shfl_xor_sync(0xffffffffu, mx, 2));
            float sum = 0.0f;
            #pragma unroll
            for (int u = 0; u < 16; u++) {
                float p = fexp(srow[g + u*4] - mx);
                srow[g + u*4] = p;
                sum += p;
            }
            sum += __shfl_xor_sync(0xffffffffu, sum, 1);
            sum += __shfl_xor_sync(0xffffffffu, sum, 2);
            float f = fexp(mold - mx);
            if (g == 0) {
                sm_m[row] = mx;
                sm_l[row] = sm_l[row] * f + sum;
                sm_f[row] = f;
            }
        }
        __syncthreads();

        // O = O*f + P @ V
        #pragma unroll
        for (int ii = 0; ii < 4; ii++) {
            float f = sm_f[ty*4 + ii];
            #pragma unroll
            for (int jj = 0; jj < 4; jj++) o[ii][jj] *= f;
        }
        #pragma unroll 8
        for (int k = 0; k < 64; k++) {
            float4 v4 = *(const float4*)(Vs + k * 64 + tx * 4);
            float p0 = Ss[(ty*4+0)*68 + k];
            float p1 = Ss[(ty*4+1)*68 + k];
            float p2 = Ss[(ty*4+2)*68 + k];
            float p3 = Ss[(ty*4+3)*68 + k];
            o[0][0] = fmaf(p0, v4.x, o[0][0]); o[0][1] = fmaf(p0, v4.y, o[0][1]);
            o[0][2] = fmaf(p0, v4.z, o[0][2]); o[0][3] = fmaf(p0, v4.w, o[0][3]);
            o[1][0] = fmaf(p1, v4.x, o[1][0]); o[1][1] = fmaf(p1, v4.y, o[1][1]);
            o[1][2] = fmaf(p1, v4.z, o[1][2]); o[1][3] = fmaf(p1, v4.w, o[1][3]);
            o[2][0] = fmaf(p2, v4.x, o[2][0]); o[2][1] = fmaf(p2, v4.y, o[2][1]);
            o[2][2] = fmaf(p2, v4.z, o[2][2]); o[2][3] = fmaf(p2, v4.w, o[2][3]);
            o[3][0] = fmaf(p3, v4.x, o[3][0]); o[3][1] = fmaf(p3, v4.y, o[3][1]);
            o[3][2] = fmaf(p3, v4.z, o[3][2]); o[3][3] = fmaf(p3, v4.w, o[3][3]);
        }
    }

    const int b = bh >> 3, h = bh & 7;
    #pragma unroll
    for (int ii = 0; ii < 4; ii++) {
        int row = ty * 4 + ii;
        float il = 1.0f / sm_l[row];
        int t = q0 + row;
        float* dst = g_ctx + ((size_t)t * B_DIM + b) * E_DIM + h * HD + tx * 4;
        *(float4*)dst = make_float4(o[ii][0]*il, o[ii][1]*il, o[ii][2]*il, o[ii][3]*il);
    }
    if (tid < 64) {
        g_m[(size_t)bh * T_DIM + q0 + tid]  = sm_m[tid];
        g_il[(size_t)bh * T_DIM + q0 + tid] = 1.0f / sm_l[tid];
    }
}

// ------------- avg_weights: recompute probs across heads, no atomics -------------
// grid: (ks=4, qt=64, b=4). block handles (b, 32 q rows, 512 k cols) in 4 chunks of 128.
__global__ void avg_kernel(float* __restrict__ outAvg)
{
    __shared__ float Qt[64 * 32];    // [d][i]
    __shared__ float Kt[64 * 128];   // [d][j]
    __shared__ float m_s[8 * 32];
    __shared__ float il_s[8 * 32];

    const int tid = threadIdx.x;
    const int b  = blockIdx.z;
    const int q0 = blockIdx.y * 32;
    const int kbase = blockIdx.x * 512;
    const int tx = tid & 31;   // k group
    const int ty = tid >> 5;   // q group (0..7)

    {
        int h = tid >> 5, i = tid & 31;
        m_s[h*32 + i]  = g_m[((size_t)(b*8 + h)) * T_DIM + q0 + i];
        il_s[h*32 + i] = g_il[((size_t)(b*8 + h)) * T_DIM + q0 + i];
    }

    for (int kc = 0; kc < 4; kc++) {
        const int k0 = kbase + kc * 128;
        float acc[4][4] = {};
        for (int h = 0; h < 8; h++) {
            __syncthreads();
            const float* Qg = g_q + ((size_t)(b*8 + h) * T_DIM + q0) * HD;
            #pragma unroll
            for (int it = 0; it < 2; it++) {
                int idx = tid + it * 256;      // 0..511
                int row = idx >> 4, d4 = idx & 15;
                float4 qv = *(const float4*)(Qg + row * HD + d4 * 4);
                Qt[(d4*4+0)*32 + row] = qv.x;
                Qt[(d4*4+1)*32 + row] = qv.y;
                Qt[(d4*4+2)*32 + row] = qv.z;
                Qt[(d4*4+3)*32 + row] = qv.w;
            }
            const float* Kg = g_k + ((size_t)(b*8 + h) * T_DIM + k0) * HD;
            #pragma unroll
            for (int it = 0; it < 8; it++) {
                int idx = tid + it * 256;      // 0..2047
                int row = idx >> 4, d4 = idx & 15;
                float4 kv = *(const float4*)(Kg + row * HD + d4 * 4);
                Kt[(d4*4+0)*128 + row] = kv.x;
                Kt[(d4*4+1)*128 + row] = kv.y;
                Kt[(d4*4+2)*128 + row] = kv.z;
                Kt[(d4*4+3)*128 + row] = kv.w;
            }
            __syncthreads();

            float s[4][4] = {};
            #pragma unroll
            for (int d = 0; d < 64; d++) {
                float4 qa = *(const float4*)(Qt + d * 32 + ty * 4);
                float4 kb = *(const float4*)(Kt + d * 128 + tx * 4);
                float a[4] = {qa.x, qa.y, qa.z, qa.w};
                float bb[4] = {kb.x, kb.y, kb.z, kb.w};
                #pragma unroll
                for (int i = 0; i < 4; i++)
                    #pragma unroll
                    for (int j = 0; j < 4; j++)
                        s[i][j] = fmaf(a[i], bb[j], s[i][j]);
            }
            #pragma unroll
            for (int ii = 0; ii < 4; ii++) {
                float m  = m_s[h*32 + ty*4 + ii];
                float il = il_s[h*32 + ty*4 + ii] * 0.125f;
                #pragma unroll
                for (int jj = 0; jj < 4; jj++)
                    acc[ii][jj] = fmaf(fexp(s[ii][jj] - m), il, acc[ii][jj]);
            }
        }
        #pragma unroll
        for (int ii = 0; ii < 4; ii++) {
            int q = q0 + ty * 4 + ii;
            float* dst = outAvg + ((size_t)b * T_DIM + q) * T_DIM + k0 + tx * 4;
            *(float4*)dst = make_float4(acc[ii][0], acc[ii][1], acc[ii][2], acc[ii][3]);
        }
    }
}

// ---------------- launch ----------------
extern "C" void kernel_launch(void* const* d_in, const int* in_sizes, int n_in,
                              void* d_out, int out_size)
{
    const float* x     = (const float*)d_in[0];   // [T,B,E]
    const float* w_in  = (const float*)d_in[1];   // [3E,E]
    const float* b_in  = (const float*)d_in[2];   // [3E]
    const float* w_out = (const float*)d_in[3];   // [E,E]
    const float* b_out = (const float*)d_in[4];   // [E]
    float* out = (float*)d_out;

    // 1. QKV projection + scatter
    {
        dim3 grid(3 * E_DIM / 64, M_ROWS / 64);
        sgemm_nt<<<grid, 256>>>(x, w_in, b_in, nullptr, 3 * E_DIM, E_DIM, 0);
    }
    // 2. flash attention
    {
        int smem = FLASH_SMEM_FLOATS * 4;
        cudaFuncSetAttribute(flash_kernel, cudaFuncAttributeMaxDynamicSharedMemorySize, smem);
        dim3 grid(T_DIM / 64, BH);
        flash_kernel<<<grid, 256, smem>>>();
    }
    // 3. avg_weights
    {
        dim3 grid(4, T_DIM / 32, B_DIM);
        avg_kernel<<<grid, 256>>>(out + ATTN_ELEMS);
    }
    // 4. out projection
    {
        dim3 grid(E_DIM / 64, M_ROWS / 64);
        sgemm_nt<<<grid, 256>>>(nullptr, w_out, b_out, out, E_DIM, E_DIM, 1);
    }
}

// round 3
// speedup vs baseline: 1.9215x; 1.9215x over previous
#include <cuda_runtime.h>
#include <cuda_bf16.h>
#include <cstdint>
#include <math.h>

#define T_DIM 2048
#define B_DIM 4
#define E_DIM 512
#define H_DIM 8
#define HD    64
#define BH    (B_DIM*H_DIM)
#define SCALE 0.125f
#define M_ROWS (T_DIM*B_DIM)
#define ATTN_ELEMS (T_DIM*B_DIM*E_DIM)

// ---------------- scratch globals ----------------
__device__ __nv_bfloat16 g_xh[M_ROWS * E_DIM];
__device__ __nv_bfloat16 g_xl[M_ROWS * E_DIM];
__device__ __nv_bfloat16 g_wih[3 * E_DIM * E_DIM];
__device__ __nv_bfloat16 g_wil[3 * E_DIM * E_DIM];
__device__ __nv_bfloat16 g_woh[E_DIM * E_DIM];
__device__ __nv_bfloat16 g_wol[E_DIM * E_DIM];
__device__ __nv_bfloat16 g_qh[BH * T_DIM * HD];
__device__ __nv_bfloat16 g_ql[BH * T_DIM * HD];
__device__ __nv_bfloat16 g_kh[BH * T_DIM * HD];
__device__ __nv_bfloat16 g_kl[BH * T_DIM * HD];
__device__ __nv_bfloat16 g_vth[BH * HD * T_DIM];   // [bh][d][t]
__device__ __nv_bfloat16 g_vtl[BH * HD * T_DIM];
__device__ __nv_bfloat16 g_ch[M_ROWS * E_DIM];     // ctx hi  [t*B+b][e]
__device__ __nv_bfloat16 g_cl[M_ROWS * E_DIM];
__device__ float g_il[BH * T_DIM];

// ---------------- helpers ----------------
__device__ __forceinline__ float fexp(float x) {
    float t = x * 1.4426950408889634f;
    t = fmaxf(t, -126.0f);
    float fl = floorf(t);
    float f  = t - fl;
    float p  = 1.5403530e-4f;
    p = fmaf(p, f, 1.3333558e-3f);
    p = fmaf(p, f, 9.6181291e-3f);
    p = fmaf(p, f, 5.5504109e-2f);
    p = fmaf(p, f, 2.4022651e-1f);
    p = fmaf(p, f, 6.9314718e-1f);
    p = fmaf(p, f, 1.0f);
    return __int_as_float(__float_as_int(p) + (((int)fl) << 23));
}

__device__ __forceinline__ uint32_t smem_u32(const void* p) {
    uint32_t a;
    asm("{ .reg .u64 t; cvta.to.shared.u64 t, %1; cvt.u32.u64 %0, t; }" : "=r"(a) : "l"(p));
    return a;
}

__device__ __forceinline__ void ldsm4(uint32_t addr, uint32_t* r) {
    asm volatile("ldmatrix.sync.aligned.m8n8.x4.shared.b16 {%0,%1,%2,%3}, [%4];"
                 : "=r"(r[0]), "=r"(r[1]), "=r"(r[2]), "=r"(r[3]) : "r"(addr));
}

__device__ __forceinline__ void mma_bf(float* c, const uint32_t* a, const uint32_t* b) {
    asm volatile("mma.sync.aligned.m16n8k16.row.col.f32.bf16.bf16.f32 "
                 "{%0,%1,%2,%3},{%4,%5,%6,%7},{%8,%9},{%0,%1,%2,%3};"
                 : "+f"(c[0]), "+f"(c[1]), "+f"(c[2]), "+f"(c[3])
                 : "r"(a[0]), "r"(a[1]), "r"(a[2]), "r"(a[3]), "r"(b[0]), "r"(b[1]));
}

// tiles: rows x 64 bf16, row pitch 128B, 16B-chunk XOR swizzle (ch ^= row&7)
__device__ __forceinline__ uint32_t addrA(uint32_t base, int m0, int kc, int lane) {
    int g = lane >> 3, r8 = lane & 7;
    int row = m0 + r8 + ((g & 1) << 3);
    int ch  = kc + (g >> 1);
    return base + row * 128 + ((ch ^ (row & 7)) << 4);
}
__device__ __forceinline__ uint32_t addrB(uint32_t base, int n0, int kc, int lane) {
    int g = lane >> 3, r8 = lane & 7;
    int row = n0 + r8 + ((g >> 1) << 3);
    int ch  = kc + (g & 1);
    return base + row * 128 + ((ch ^ (row & 7)) << 4);
}

// 32x32 warp tile, one 16-wide k-step, 3 split passes (hi*hi + hi*lo + lo*hi)
__device__ __forceinline__ void warp_step(float c[2][4][4],
    uint32_t AHb, uint32_t ALb, uint32_t BHb, uint32_t BLb,
    int wm0, int wn0, int kc, int lane)
{
    uint32_t ah[2][4], al[2][4], bhf[4][2], blf[4][2];
    #pragma unroll
    for (int i = 0; i < 2; i++) {
        ldsm4(addrA(AHb, wm0 + i * 16, kc, lane), ah[i]);
        ldsm4(addrA(ALb, wm0 + i * 16, kc, lane), al[i]);
    }
    #pragma unroll
    for (int jj = 0; jj < 2; jj++) {
        uint32_t t[4];
        ldsm4(addrB(BHb, wn0 + jj * 16, kc, lane), t);
        bhf[jj*2][0] = t[0]; bhf[jj*2][1] = t[1];
        bhf[jj*2+1][0] = t[2]; bhf[jj*2+1][1] = t[3];
        ldsm4(addrB(BLb, wn0 + jj * 16, kc, lane), t);
        blf[jj*2][0] = t[0]; blf[jj*2][1] = t[1];
        blf[jj*2+1][0] = t[2]; blf[jj*2+1][1] = t[3];
    }
    #pragma unroll
    for (int i = 0; i < 2; i++)
        #pragma unroll
        for (int j = 0; j < 4; j++) {
            mma_bf(c[i][j], ah[i], bhf[j]);
            mma_bf(c[i][j], ah[i], blf[j]);
            mma_bf(c[i][j], al[i], bhf[j]);
        }
}

// global -> swizzled smem tile (rows x 64 bf16)
__device__ __forceinline__ void load_tile(char* dst, const __nv_bfloat16* g,
                                          int rows, int gstride, int tid, int nthr)
{
    for (int idx = tid; idx < rows * 8; idx += nthr) {
        int r = idx >> 3, ch = idx & 7;
        *(uint4*)(dst + r * 128 + ((ch ^ (r & 7)) << 4)) =
            *(const uint4*)(g + (size_t)r * gstride + ch * 8);
    }
}

__device__ __forceinline__ uint32_t packsplit(float x, float y, uint32_t* lo) {
    __nv_bfloat16 hx = __float2bfloat16(x), hy = __float2bfloat16(y);
    __nv_bfloat16 lx = __float2bfloat16(x - __bfloat162float(hx));
    __nv_bfloat16 ly = __float2bfloat16(y - __bfloat162float(hy));
    __nv_bfloat162 hv; hv.x = hx; hv.y = hy;
    __nv_bfloat162 lv; lv.x = lx; lv.y = ly;
    *lo = *(uint32_t*)&lv;
    return *(uint32_t*)&hv;
}

// ---------------- split kernels ----------------
__global__ void split_f32(const float* __restrict__ src, int n, int which)
{
    __nv_bfloat16 *hi, *lo;
    if (which == 0)      { hi = g_xh;  lo = g_xl;  }
    else if (which == 1) { hi = g_wih; lo = g_wil; }
    else                 { hi = g_woh; lo = g_wol; }
    int i = blockIdx.x * blockDim.x + threadIdx.x;
    if (i < n) {
        float v = src[i];
        __nv_bfloat16 h = __float2bfloat16(v);
        hi[i] = h;
        lo[i] = __float2bfloat16(v - __bfloat162float(h));
    }
}

// ---------------- projection GEMM (bf16 split MMA) ----------------
// mode 0: in-proj  (A=x, B=w_in,  N=1536, scatter epilogue)
// mode 1: out-proj (A=ctx, B=w_out, N=512, fp32 epilogue)
__global__ __launch_bounds__(256) void gemm_mma(const float* __restrict__ bias,
                                                float* __restrict__ C, int mode)
{
    extern __shared__ char smem[];
    const int Kd = 512;
    const __nv_bfloat16 *Ah, *Al, *Bh, *Bl;
    if (mode == 0) { Ah = g_xh; Al = g_xl; Bh = g_wih; Bl = g_wil; }
    else           { Ah = g_ch; Al = g_cl; Bh = g_woh; Bl = g_wol; }

    const uint32_t sb = smem_u32(smem);
    const uint32_t AHo = 0, ALo = 16384, BHo = 32768, BLo = 40960;
    const int tid = threadIdx.x, lane = tid & 31, wid = tid >> 5;
    const int wm0 = (wid & 3) * 32, wn0 = (wid >> 2) * 32;
    const int m0 = blockIdx.y * 128, n0 = blockIdx.x * 64;

    float c[2][4][4] = {};
    for (int ko = 0; ko < Kd; ko += 64) {
        load_tile(smem + AHo, Ah + (size_t)m0 * Kd + ko, 128, Kd, tid, 256);
        load_tile(smem + ALo, Al + (size_t)m0 * Kd + ko, 128, Kd, tid, 256);
        load_tile(smem + BHo, Bh + (size_t)n0 * Kd + ko, 64, Kd, tid, 256);
        load_tile(smem + BLo, Bl + (size_t)n0 * Kd + ko, 64, Kd, tid, 256);
        __syncthreads();
        #pragma unroll
        for (int kc = 0; kc < 8; kc += 2)
            warp_step(c, sb + AHo, sb + ALo, sb + BHo, sb + BLo, wm0, wn0, kc, lane);
        __syncthreads();
    }

    #pragma unroll
    for (int i = 0; i < 2; i++)
        #pragma unroll
        for (int j = 0; j < 4; j++)
            #pragma unroll
            for (int e = 0; e < 4; e++) {
                int rg = m0 + wm0 + i * 16 + (lane >> 2) + ((e >> 1) << 3);
                int n  = n0 + wn0 + j * 8 + (lane & 3) * 2 + (e & 1);
                float v = c[i][j][e] + bias[n];
                if (mode == 0) {
                    int t = rg >> 2, bb = rg & 3;
                    int sect = n >> 9, jm = n & 511;
                    int hh = jm >> 6, d = jm & 63;
                    int bh = bb * 8 + hh;
                    if (sect == 2) {
                        size_t dst = ((size_t)bh * HD + d) * T_DIM + t;
                        __nv_bfloat16 h = __float2bfloat16(v);
                        g_vth[dst] = h;
                        g_vtl[dst] = __float2bfloat16(v - __bfloat162float(h));
                    } else {
                        size_t dst = ((size_t)bh * T_DIM + t) * HD + d;
                        if (sect == 0) {
                            v *= SCALE;
                            __nv_bfloat16 h = __float2bfloat16(v);
                            g_qh[dst] = h;
                            g_ql[dst] = __float2bfloat16(v - __bfloat162float(h));
                        } else {
                            __nv_bfloat16 h = __float2bfloat16(v);
                            g_kh[dst] = h;
                            g_kl[dst] = __float2bfloat16(v - __bfloat162float(h));
                        }
                    }
                } else {
                    C[(size_t)rg * E_DIM + n] = v;
                }
            }
}

// ---------------- flash attention (warp MMA) ----------------
// smem: QH 0, QL 16384, KH 32768, KL 40960, VH 49152, VL 57344,
//       PH 65536, PL 81920, RS 98304 (2*128 floats)
#define F_SMEM 99328

__global__ __launch_bounds__(256) void flash_mma()
{
    extern __shared__ char smem[];
    const uint32_t sb = smem_u32(smem);
    const int tid = threadIdx.x, lane = tid & 31, wid = tid >> 5;
    const int wm0 = (wid & 3) * 32, wn0 = (wid >> 2) * 32;
    const int bh = blockIdx.y, q0 = blockIdx.x * 128;
    const int b = bh >> 3, h = bh & 7;
    float* RS = (float*)(smem + 98304);

    load_tile(smem,         g_qh + ((size_t)bh * T_DIM + q0) * HD, 128, HD, tid, 256);
    load_tile(smem + 16384, g_ql + ((size_t)bh * T_DIM + q0) * HD, 128, HD, tid, 256);

    float o[2][4][4] = {};
    float rs4[4] = {};

    for (int kt = 0; kt < T_DIM / 64; kt++) {
        const int k0 = kt * 64;
        load_tile(smem + 32768, g_kh + ((size_t)bh * T_DIM + k0) * HD, 64, HD, tid, 256);
        load_tile(smem + 40960, g_kl + ((size_t)bh * T_DIM + k0) * HD, 64, HD, tid, 256);
        load_tile(smem + 49152, g_vth + (size_t)bh * HD * T_DIM + k0, 64, T_DIM, tid, 256);
        load_tile(smem + 57344, g_vtl + (size_t)bh * HD * T_DIM + k0, 64, T_DIM, tid, 256);
        __syncthreads();

        // S = Q K^T (128x64)
        float s[2][4][4] = {};
        #pragma unroll
        for (int kc = 0; kc < 8; kc += 2)
            warp_step(s, sb, sb + 16384, sb + 32768, sb + 40960, wm0, wn0, kc, lane);

        // exp + row-sum + store P hi/lo
        #pragma unroll
        for (int i = 0; i < 2; i++)
            #pragma unroll
            for (int j = 0; j < 4; j++) {
                #pragma unroll
                for (int e = 0; e < 4; e++) {
                    float p = fexp(s[i][j][e]);
                    s[i][j][e] = p;
                    rs4[i * 2 + (e >> 1)] += p;
                }
                #pragma unroll
                for (int hf = 0; hf < 2; hf++) {
                    int row = wm0 + i * 16 + (lane >> 2) + hf * 8;
                    int cc  = wn0 + j * 8 + (lane & 3) * 2;
                    uint32_t off = row * 128 + (((cc >> 3) ^ (row & 7)) << 4) + (cc & 7) * 2;
                    uint32_t lo;
                    uint32_t hi = packsplit(s[i][j][hf * 2], s[i][j][hf * 2 + 1], &lo);
                    *(uint32_t*)(smem + 65536 + off) = hi;
                    *(uint32_t*)(smem + 81920 + off) = lo;
                }
            }
        __syncthreads();

        // O += P V  (A=P 128x64, B=Vt 64x64)
        #pragma unroll
        for (int kc = 0; kc < 8; kc += 2)
            warp_step(o, sb + 65536, sb + 81920, sb + 49152, sb + 57344, wm0, wn0, kc, lane);
        __syncthreads();
    }

    // reduce row sums across quad, then across the two n-half warps via smem
    #pragma unroll
    for (int x = 0; x < 4; x++) {
        rs4[x] += __shfl_xor_sync(0xffffffffu, rs4[x], 1);
        rs4[x] += __shfl_xor_sync(0xffffffffu, rs4[x], 2);
    }
    if ((lane & 3) == 0) {
        #pragma unroll
        for (int i = 0; i < 2; i++)
            #pragma unroll
            for (int hf = 0; hf < 2; hf++)
                RS[(wid >> 2) * 128 + wm0 + i * 16 + (lane >> 2) + hf * 8] = rs4[i * 2 + hf];
    }
    __syncthreads();

    #pragma unroll
    for (int i = 0; i < 2; i++)
        #pragma unroll
        for (int hf = 0; hf < 2; hf++) {
            int r = wm0 + i * 16 + (lane >> 2) + hf * 8;
            float il = 1.0f / (RS[r] + RS[128 + r]);
            #pragma unroll
            for (int j = 0; j < 4; j++) {
                int cc = wn0 + j * 8 + (lane & 3) * 2;
                uint32_t lo;
                uint32_t hi = packsplit(o[i][j][hf * 2] * il, o[i][j][hf * 2 + 1] * il, &lo);
                size_t off = ((size_t)(q0 + r) * B_DIM + b) * E_DIM + h * HD + cc;
                *(uint32_t*)&g_ch[off] = hi;
                *(uint32_t*)&g_cl[off] = lo;
            }
            if (wn0 == 0 && (lane & 3) == 0)
                g_il[(size_t)bh * T_DIM + q0 + r] = il;
        }
}

// ---------------- avg_weights (warp MMA recompute) ----------------
// smem: QH 0, QL 16384, KH 32768, KL 40960 -> 49152 bytes
__global__ __launch_bounds__(256) void avg_mma(float* __restrict__ outAvg)
{
    extern __shared__ char smem[];
    const uint32_t sb = smem_u32(smem);
    const int tid = threadIdx.x, lane = tid & 31, wid = tid >> 5;
    const int wm0 = (wid & 3) * 32, wn0 = (wid >> 2) * 32;
    const int b = blockIdx.z, q0 = blockIdx.y * 128, k0 = blockIdx.x * 64;

    float av[2][4][4] = {};

    for (int hh = 0; hh < H_DIM; hh++) {
        const int bh = b * 8 + hh;
        load_tile(smem,         g_qh + ((size_t)bh * T_DIM + q0) * HD, 128, HD, tid, 256);
        load_tile(smem + 16384, g_ql + ((size_t)bh * T_DIM + q0) * HD, 128, HD, tid, 256);
        load_tile(smem + 32768, g_kh + ((size_t)bh * T_DIM + k0) * HD, 64, HD, tid, 256);
        load_tile(smem + 40960, g_kl + ((size_t)bh * T_DIM + k0) * HD, 64, HD, tid, 256);
        __syncthreads();

        float s[2][4][4] = {};
        #pragma unroll
        for (int kc = 0; kc < 8; kc += 2)
            warp_step(s, sb, sb + 16384, sb + 32768, sb + 40960, wm0, wn0, kc, lane);

        float il4[4];
        #pragma unroll
        for (int i = 0; i < 2; i++)
            #pragma unroll
            for (int hf = 0; hf < 2; hf++)
                il4[i * 2 + hf] =
                    g_il[(size_t)bh * T_DIM + q0 + wm0 + i * 16 + (lane >> 2) + hf * 8] * 0.125f;

        #pragma unroll
        for (int i = 0; i < 2; i++)
            #pragma unroll
            for (int j = 0; j < 4; j++)
                #pragma unroll
                for (int e = 0; e < 4; e++)
                    av[i][j][e] = fmaf(fexp(s[i][j][e]), il4[i * 2 + (e >> 1)], av[i][j][e]);
        __syncthreads();
    }

    #pragma unroll
    for (int i = 0; i < 2; i++)
        #pragma unroll
        for (int hf = 0; hf < 2; hf++) {
            int r = wm0 + i * 16 + (lane >> 2) + hf * 8;
            #pragma unroll
            for (int j = 0; j < 4; j++) {
                int cc = k0 + wn0 + j * 8 + (lane & 3) * 2;
                *(float2*)(outAvg + ((size_t)b * T_DIM + q0 + r) * T_DIM + cc) =
                    make_float2(av[i][j][hf * 2], av[i][j][hf * 2 + 1]);
            }
        }
}

// ---------------- launch ----------------
extern "C" void kernel_launch(void* const* d_in, const int* in_sizes, int n_in,
                              void* d_out, int out_size)
{
    const float* x     = (const float*)d_in[0];
    const float* w_in  = (const float*)d_in[1];
    const float* b_in  = (const float*)d_in[2];
    const float* w_out = (const float*)d_in[3];
    const float* b_out = (const float*)d_in[4];
    float* out = (float*)d_out;

    split_f32<<<(M_ROWS * E_DIM + 255) / 256, 256>>>(x, M_ROWS * E_DIM, 0);
    split_f32<<<(3 * E_DIM * E_DIM + 255) / 256, 256>>>(w_in, 3 * E_DIM * E_DIM, 1);
    split_f32<<<(E_DIM * E_DIM + 255) / 256, 256>>>(w_out, E_DIM * E_DIM, 2);

    cudaFuncSetAttribute(gemm_mma, cudaFuncAttributeMaxDynamicSharedMemorySize, 49152);
    gemm_mma<<<dim3(3 * E_DIM / 64, M_ROWS / 128), 256, 49152>>>(b_in, out, 0);

    cudaFuncSetAttribute(flash_mma, cudaFuncAttributeMaxDynamicSharedMemorySize, F_SMEM);
    flash_mma<<<dim3(T_DIM / 128, BH), 256, F_SMEM>>>();

    cudaFuncSetAttribute(avg_mma, cudaFuncAttributeMaxDynamicSharedMemorySize, 49152);
    avg_mma<<<dim3(T_DIM / 64, T_DIM / 128, B_DIM), 256, 49152>>>(out + ATTN_ELEMS);

    gemm_mma<<<dim3(E_DIM / 64, M_ROWS / 128), 256, 49152>>>(b_out, out, 1);
}

// round 5
// speedup vs baseline: 4.1306x; 2.1497x over previous
#include <cuda_runtime.h>
#include <cuda_bf16.h>
#include <cuda_fp16.h>
#include <cstdint>
#include <math.h>

#define T_DIM 2048
#define B_DIM 4
#define E_DIM 512
#define H_DIM 8
#define HD    64
#define BH    (B_DIM*H_DIM)
#define SCALE 0.125f
#define M_ROWS (T_DIM*B_DIM)
#define ATTN_ELEMS (T_DIM*B_DIM*E_DIM)

// ---------------- scratch globals ----------------
__device__ __nv_bfloat16 g_xh[M_ROWS * E_DIM];
__device__ __nv_bfloat16 g_xl[M_ROWS * E_DIM];
__device__ __nv_bfloat16 g_wih[3 * E_DIM * E_DIM];
__device__ __nv_bfloat16 g_wil[3 * E_DIM * E_DIM];
__device__ __nv_bfloat16 g_woh[E_DIM * E_DIM];
__device__ __nv_bfloat16 g_wol[E_DIM * E_DIM];
__device__ __nv_bfloat16 g_qh[BH * T_DIM * HD];
__device__ __nv_bfloat16 g_ql[BH * T_DIM * HD];
__device__ __nv_bfloat16 g_kh[BH * T_DIM * HD];
__device__ __nv_bfloat16 g_kl[BH * T_DIM * HD];
__device__ __nv_bfloat16 g_vth[BH * HD * T_DIM];   // [bh][d][t]
__device__ __nv_bfloat16 g_vtl[BH * HD * T_DIM];
__device__ __nv_bfloat16 g_ch[M_ROWS * E_DIM];     // ctx hi  [t*B+b][e]
__device__ __nv_bfloat16 g_cl[M_ROWS * E_DIM];
__device__ float g_il[BH * T_DIM];
__device__ __align__(16) __half g_p[(size_t)BH * T_DIM * T_DIM];  // 256MB, exp(s) unnormalized

// ---------------- helpers ----------------
__device__ __forceinline__ float fexp(float x) {
    float t = x * 1.4426950408889634f;
    t = fmaxf(t, -126.0f);
    float fl = floorf(t);
    float f  = t - fl;
    float p  = 1.5403530e-4f;
    p = fmaf(p, f, 1.3333558e-3f);
    p = fmaf(p, f, 9.6181291e-3f);
    p = fmaf(p, f, 5.5504109e-2f);
    p = fmaf(p, f, 2.4022651e-1f);
    p = fmaf(p, f, 6.9314718e-1f);
    p = fmaf(p, f, 1.0f);
    return __int_as_float(__float_as_int(p) + (((int)fl) << 23));
}

__device__ __forceinline__ uint32_t smem_u32(const void* p) {
    uint32_t a;
    asm("{ .reg .u64 t; cvta.to.shared.u64 t, %1; cvt.u32.u64 %0, t; }" : "=r"(a) : "l"(p));
    return a;
}

__device__ __forceinline__ void ldsm4(uint32_t addr, uint32_t* r) {
    asm volatile("ldmatrix.sync.aligned.m8n8.x4.shared.b16 {%0,%1,%2,%3}, [%4];"
                 : "=r"(r[0]), "=r"(r[1]), "=r"(r[2]), "=r"(r[3]) : "r"(addr));
}

__device__ __forceinline__ void mma_bf(float* c, const uint32_t* a, const uint32_t* b) {
    asm volatile("mma.sync.aligned.m16n8k16.row.col.f32.bf16.bf16.f32 "
                 "{%0,%1,%2,%3},{%4,%5,%6,%7},{%8,%9},{%0,%1,%2,%3};"
                 : "+f"(c[0]), "+f"(c[1]), "+f"(c[2]), "+f"(c[3])
                 : "r"(a[0]), "r"(a[1]), "r"(a[2]), "r"(a[3]), "r"(b[0]), "r"(b[1]));
}

__device__ __forceinline__ void cpa16(uint32_t dst, const void* src) {
    asm volatile("cp.async.cg.shared.global [%0], [%1], 16;" :: "r"(dst), "l"(src));
}
#define CP_COMMIT() asm volatile("cp.async.commit_group;" ::: "memory")
#define CP_WAIT1()  asm volatile("cp.async.wait_group 1;" ::: "memory")

// tiles: rows x 64 bf16, row pitch 128B, 16B-chunk XOR swizzle
__device__ __forceinline__ uint32_t addrA(uint32_t base, int m0, int kc, int lane) {
    int g = lane >> 3, r8 = lane & 7;
    int row = m0 + r8 + ((g & 1) << 3);
    int ch  = kc + (g >> 1);
    return base + row * 128 + ((ch ^ (row & 7)) << 4);
}
__device__ __forceinline__ uint32_t addrB(uint32_t base, int n0, int kc, int lane) {
    int g = lane >> 3, r8 = lane & 7;
    int row = n0 + r8 + ((g >> 1) << 3);
    int ch  = kc + (g & 1);
    return base + row * 128 + ((ch ^ (row & 7)) << 4);
}

// 32x32 warp tile step for projection GEMMs (3 split passes)
__device__ __forceinline__ void warp_step(float c[2][4][4],
    uint32_t AHb, uint32_t ALb, uint32_t BHb, uint32_t BLb,
    int wm0, int wn0, int kc, int lane)
{
    uint32_t ah[2][4], al[2][4], bhf[4][2], blf[4][2];
    #pragma unroll
    for (int i = 0; i < 2; i++) {
        ldsm4(addrA(AHb, wm0 + i * 16, kc, lane), ah[i]);
        ldsm4(addrA(ALb, wm0 + i * 16, kc, lane), al[i]);
    }
    #pragma unroll
    for (int jj = 0; jj < 2; jj++) {
        uint32_t t[4];
        ldsm4(addrB(BHb, wn0 + jj * 16, kc, lane), t);
        bhf[jj*2][0] = t[0]; bhf[jj*2][1] = t[1];
        bhf[jj*2+1][0] = t[2]; bhf[jj*2+1][1] = t[3];
        ldsm4(addrB(BLb, wn0 + jj * 16, kc, lane), t);
        blf[jj*2][0] = t[0]; blf[jj*2][1] = t[1];
        blf[jj*2+1][0] = t[2]; blf[jj*2+1][1] = t[3];
    }
    #pragma unroll
    for (int i = 0; i < 2; i++)
        #pragma unroll
        for (int j = 0; j < 4; j++) {
            mma_bf(c[i][j], ah[i], bhf[j]);
            mma_bf(c[i][j], ah[i], blf[j]);
            mma_bf(c[i][j], al[i], bhf[j]);
        }
}

__device__ __forceinline__ uint32_t packsplit(float x, float y, uint32_t* lo) {
    __nv_bfloat16 hx = __float2bfloat16(x), hy = __float2bfloat16(y);
    __nv_bfloat16 lx = __float2bfloat16(x - __bfloat162float(hx));
    __nv_bfloat16 ly = __float2bfloat16(y - __bfloat162float(hy));
    __nv_bfloat162 hv; hv.x = hx; hv.y = hy;
    __nv_bfloat162 lv; lv.x = lx; lv.y = ly;
    *lo = *(uint32_t*)&lv;
    return *(uint32_t*)&hv;
}

// ---------------- split kernels ----------------
__global__ void split_f32(const float* __restrict__ src, int n, int which)
{
    __nv_bfloat16 *hi, *lo;
    if (which == 0)      { hi = g_xh;  lo = g_xl;  }
    else if (which == 1) { hi = g_wih; lo = g_wil; }
    else                 { hi = g_woh; lo = g_wol; }
    int i = blockIdx.x * blockDim.x + threadIdx.x;
    if (i < n) {
        float v = src[i];
        __nv_bfloat16 h = __float2bfloat16(v);
        hi[i] = h;
        lo[i] = __float2bfloat16(v - __bfloat162float(h));
    }
}

// ---------------- projection GEMM (cp.async double-buffered) ----------------
// stage layout: AH 0, AL 16384, BH 32768, BL 40960  (stage size 49152, 2 stages)
__device__ __forceinline__ void gemm_issue(uint32_t stage_base,
    const __nv_bfloat16* Ah, const __nv_bfloat16* Al,
    const __nv_bfloat16* Bh, const __nv_bfloat16* Bl,
    int m0, int n0, int ko, int tid)
{
    #pragma unroll
    for (int i = 0; i < 4; i++) {
        int idx = tid + i * 256;          // 0..1023
        int r = idx >> 3, ch = idx & 7;
        uint32_t off = r * 128 + ((ch ^ (r & 7)) << 4);
        cpa16(stage_base + off,         Ah + (size_t)(m0 + r) * E_DIM + ko + ch * 8);
        cpa16(stage_base + 16384 + off, Al + (size_t)(m0 + r) * E_DIM + ko + ch * 8);
    }
    #pragma unroll
    for (int i = 0; i < 2; i++) {
        int idx = tid + i * 256;          // 0..511
        int r = idx >> 3, ch = idx & 7;
        uint32_t off = r * 128 + ((ch ^ (r & 7)) << 4);
        cpa16(stage_base + 32768 + off, Bh + (size_t)(n0 + r) * E_DIM + ko + ch * 8);
        cpa16(stage_base + 40960 + off, Bl + (size_t)(n0 + r) * E_DIM + ko + ch * 8);
    }
}

__global__ __launch_bounds__(256) void gemm_mma(const float* __restrict__ bias,
                                                float* __restrict__ C, int mode)
{
    extern __shared__ char smem[];
    const __nv_bfloat16 *Ah, *Al, *Bh, *Bl;
    if (mode == 0) { Ah = g_xh; Al = g_xl; Bh = g_wih; Bl = g_wil; }
    else           { Ah = g_ch; Al = g_cl; Bh = g_woh; Bl = g_wol; }

    const uint32_t sb = smem_u32(smem);
    const int tid = threadIdx.x, lane = tid & 31, wid = tid >> 5;
    const int wm0 = (wid & 3) * 32, wn0 = (wid >> 2) * 32;
    const int m0 = blockIdx.y * 128, n0 = blockIdx.x * 64;

    gemm_issue(sb,         Ah, Al, Bh, Bl, m0, n0, 0,  tid); CP_COMMIT();
    gemm_issue(sb + 49152, Ah, Al, Bh, Bl, m0, n0, 64, tid); CP_COMMIT();

    float c[2][4][4] = {};
    for (int s = 0; s < 8; s++) {
        CP_WAIT1();
        __syncthreads();
        uint32_t st = sb + (s & 1) * 49152;
        #pragma unroll
        for (int kc = 0; kc < 8; kc += 2)
            warp_step(c, st, st + 16384, st + 32768, st + 40960, wm0, wn0, kc, lane);
        __syncthreads();
        if (s + 2 < 8)
            gemm_issue(sb + (s & 1) * 49152, Ah, Al, Bh, Bl, m0, n0, (s + 2) * 64, tid);
        CP_COMMIT();
    }

    #pragma unroll
    for (int i = 0; i < 2; i++)
        #pragma unroll
        for (int j = 0; j < 4; j++)
            #pragma unroll
            for (int e = 0; e < 4; e++) {
                int rg = m0 + wm0 + i * 16 + (lane >> 2) + ((e >> 1) << 3);
                int n  = n0 + wn0 + j * 8 + (lane & 3) * 2 + (e & 1);
                float v = c[i][j][e] + bias[n];
                if (mode == 0) {
                    int t = rg >> 2, bb = rg & 3;
                    int sect = n >> 9, jm = n & 511;
                    int hh = jm >> 6, d = jm & 63;
                    int bh = bb * 8 + hh;
                    if (sect == 2) {
                        size_t dst = ((size_t)bh * HD + d) * T_DIM + t;
                        __nv_bfloat16 h = __float2bfloat16(v);
                        g_vth[dst] = h;
                        g_vtl[dst] = __float2bfloat16(v - __bfloat162float(h));
                    } else {
                        size_t dst = ((size_t)bh * T_DIM + t) * HD + d;
                        if (sect == 0) {
                            v *= SCALE;
                            __nv_bfloat16 h = __float2bfloat16(v);
                            g_qh[dst] = h;
                            g_ql[dst] = __float2bfloat16(v - __bfloat162float(h));
                        } else {
                            __nv_bfloat16 h = __float2bfloat16(v);
                            g_kh[dst] = h;
                            g_kl[dst] = __float2bfloat16(v - __bfloat162float(h));
                        }
                    }
                } else {
                    C[(size_t)rg * E_DIM + n] = v;
                }
            }
}

// ---------------- flash attention: register-resident PV ----------------
// 128 threads (4 warps), q-tile 128 (32 rows/warp, full k width per warp).
// smem: QH 0, QL 16384, KVbuf0 32768, KVbuf1 65536
//   buf: KH +0, KL +8192, VH +16384, VL +24576   -> total 98304
__device__ __forceinline__ void flash_issue_kv(uint32_t buf, int bh, int k0, int tid)
{
    #pragma unroll
    for (int i = 0; i < 4; i++) {
        int idx = tid + i * 128;          // 0..511
        int r = idx >> 3, ch = idx & 7;
        uint32_t off = r * 128 + ((ch ^ (r & 7)) << 4);
        const size_t kof = ((size_t)bh * T_DIM + k0 + r) * HD + ch * 8;
        const size_t vof = ((size_t)bh * HD + r) * T_DIM + k0 + ch * 8;
        cpa16(buf + off,         g_kh + kof);
        cpa16(buf + 8192 + off,  g_kl + kof);
        cpa16(buf + 16384 + off, g_vth + vof);
        cpa16(buf + 24576 + off, g_vtl + vof);
    }
}

__global__ __launch_bounds__(128, 2) void flash_mma()
{
    extern __shared__ char smem[];
    const uint32_t sb = smem_u32(smem);
    const int tid = threadIdx.x, lane = tid & 31, w = tid >> 5;
    const int bh = blockIdx.y, q0 = blockIdx.x * 128;
    const int b = bh >> 3, h = bh & 7;
    const int wq0 = w * 32;

    // prefetch KV tiles 0,1
    flash_issue_kv(sb + 32768, bh, 0, tid);  CP_COMMIT();
    flash_issue_kv(sb + 65536, bh, 64, tid); CP_COMMIT();

    // load Q hi/lo to smem (plain)
    {
        const __nv_bfloat16* Qh = g_qh + ((size_t)bh * T_DIM + q0) * HD;
        const __nv_bfloat16* Ql = g_ql + ((size_t)bh * T_DIM + q0) * HD;
        #pragma unroll
        for (int i = 0; i < 8; i++) {
            int idx = tid + i * 128;      // 0..1023
            int r = idx >> 3, ch = idx & 7;
            uint32_t off = r * 128 + ((ch ^ (r & 7)) << 4);
            *(uint4*)(smem + off)         = *(const uint4*)(Qh + (size_t)r * HD + ch * 8);
            *(uint4*)(smem + 16384 + off) = *(const uint4*)(Ql + (size_t)r * HD + ch * 8);
        }
    }
    __syncthreads();

    // cache Q fragments in registers (for all 32 k-tiles)
    uint32_t qh[2][4][4], ql[2][4][4];
    #pragma unroll
    for (int i = 0; i < 2; i++)
        #pragma unroll
        for (int kk = 0; kk < 4; kk++) {
            ldsm4(addrA(sb,         wq0 + i * 16, 2 * kk, lane), qh[i][kk]);
            ldsm4(addrA(sb + 16384, wq0 + i * 16, 2 * kk, lane), ql[i][kk]);
        }

    float o[2][8][4] = {};
    float rs[4] = {};

    for (int kt = 0; kt < T_DIM / 64; kt++) {
        CP_WAIT1();
        __syncthreads();
        const uint32_t buf = sb + 32768 + (kt & 1) * 32768;

        // S = Q K^T  (32 x 64 per warp)
        float s[2][8][4] = {};
        #pragma unroll
        for (int kk = 0; kk < 4; kk++)
            #pragma unroll
            for (int jj = 0; jj < 4; jj++) {
                uint32_t th[4], tl[4];
                ldsm4(addrB(buf,        jj * 16, 2 * kk, lane), th);
                ldsm4(addrB(buf + 8192, jj * 16, 2 * kk, lane), tl);
                uint32_t bh0[2] = {th[0], th[1]}, bh1[2] = {th[2], th[3]};
                uint32_t bl0[2] = {tl[0], tl[1]}, bl1[2] = {tl[2], tl[3]};
                #pragma unroll
                for (int i = 0; i < 2; i++) {
                    mma_bf(s[i][jj*2], qh[i][kk], bh0);
                    mma_bf(s[i][jj*2], qh[i][kk], bl0);
                    mma_bf(s[i][jj*2], ql[i][kk], bh0);
                    mma_bf(s[i][jj*2+1], qh[i][kk], bh1);
                    mma_bf(s[i][jj*2+1], qh[i][kk], bl1);
                    mma_bf(s[i][jj*2+1], ql[i][kk], bh1);
                }
            }

        // exp in place + row sums + stream P to gmem
        #pragma unroll
        for (int i = 0; i < 2; i++)
            #pragma unroll
            for (int j = 0; j < 8; j++) {
                float p0 = fexp(s[i][j][0]), p1 = fexp(s[i][j][1]);
                float p2 = fexp(s[i][j][2]), p3 = fexp(s[i][j][3]);
                s[i][j][0] = p0; s[i][j][1] = p1; s[i][j][2] = p2; s[i][j][3] = p3;
                rs[i*2]   += p0 + p1;
                rs[i*2+1] += p2 + p3;
                int col = kt * 64 + j * 8 + (lane & 3) * 2;
                int r0 = q0 + wq0 + i * 16 + (lane >> 2);
                __half2* d0 = (__half2*)(g_p + ((size_t)bh * T_DIM + r0) * T_DIM + col);
                __half2* d1 = (__half2*)(g_p + ((size_t)bh * T_DIM + r0 + 8) * T_DIM + col);
                __stcs(d0, __floats2half2_rn(p0, p1));
                __stcs(d1, __floats2half2_rn(p2, p3));
            }

        // pack P into PV A-fragments (registers only)
        uint32_t aPh[2][4][4], aPl[2][4][4];
        #pragma unroll
        for (int i = 0; i < 2; i++)
            #pragma unroll
            for (int kk = 0; kk < 4; kk++) {
                aPh[i][kk][0] = packsplit(s[i][2*kk][0],   s[i][2*kk][1],   &aPl[i][kk][0]);
                aPh[i][kk][1] = packsplit(s[i][2*kk][2],   s[i][2*kk][3],   &aPl[i][kk][1]);
                aPh[i][kk][2] = packsplit(s[i][2*kk+1][0], s[i][2*kk+1][1], &aPl[i][kk][2]);
                aPh[i][kk][3] = packsplit(s[i][2*kk+1][2], s[i][2*kk+1][3], &aPl[i][kk][3]);
            }

        // O += P V  (B = Vt in smem)
        #pragma unroll
        for (int kk = 0; kk < 4; kk++)
            #pragma unroll
            for (int jj = 0; jj < 4; jj++) {
                uint32_t th[4], tl[4];
                ldsm4(addrB(buf + 16384, jj * 16, 2 * kk, lane), th);
                ldsm4(addrB(buf + 24576, jj * 16, 2 * kk, lane), tl);
                uint32_t bh0[2] = {th[0], th[1]}, bh1[2] = {th[2], th[3]};
                uint32_t bl0[2] = {tl[0], tl[1]}, bl1[2] = {tl[2], tl[3]};
                #pragma unroll
                for (int i = 0; i < 2; i++) {
                    mma_bf(o[i][jj*2], aPh[i][kk], bh0);
                    mma_bf(o[i][jj*2], aPh[i][kk], bl0);
                    mma_bf(o[i][jj*2], aPl[i][kk], bh0);
                    mma_bf(o[i][jj*2+1], aPh[i][kk], bh1);
                    mma_bf(o[i][jj*2+1], aPh[i][kk], bl1);
                    mma_bf(o[i][jj*2+1], aPl[i][kk], bh1);
                }
            }
        __syncthreads();
        if (kt + 2 < T_DIM / 64)
            flash_issue_kv(sb + 32768 + (kt & 1) * 32768, bh, (kt + 2) * 64, tid);
        CP_COMMIT();
    }

    // quad-reduce row sums (each warp owns its rows fully)
    #pragma unroll
    for (int x = 0; x < 4; x++) {
        rs[x] += __shfl_xor_sync(0xffffffffu, rs[x], 1);
        rs[x] += __shfl_xor_sync(0xffffffffu, rs[x], 2);
    }
    float il[4] = {1.0f / rs[0], 1.0f / rs[1], 1.0f / rs[2], 1.0f / rs[3]};

    // write ctx (bf16 hi/lo) and 1/l
    #pragma unroll
    for (int i = 0; i < 2; i++)
        #pragma unroll
        for (int hf = 0; hf < 2; hf++) {
            int r = wq0 + i * 16 + (lane >> 2) + hf * 8;
            float s_il = il[i*2 + hf];
            #pragma unroll
            for (int j = 0; j < 8; j++) {
                int cc = j * 8 + (lane & 3) * 2;
                uint32_t lo;
                uint32_t hi = packsplit(o[i][j][hf*2] * s_il, o[i][j][hf*2+1] * s_il, &lo);
                size_t off = ((size_t)(q0 + r) * B_DIM + b) * E_DIM + h * HD + cc;
                *(uint32_t*)&g_ch[off] = hi;
                *(uint32_t*)&g_cl[off] = lo;
            }
            if ((lane & 3) == 0)
                g_il[(size_t)bh * T_DIM + q0 + r] = s_il;
        }
}

// ---------------- avg_weights: pure memory pass over stored P ----------------
__global__ __launch_bounds__(256) void avg_sum(float* __restrict__ outAvg)
{
    const int blk = blockIdx.x;           // b*T + q
    const int b = blk >> 11, q = blk & 2047;
    const int tid = threadIdx.x;

    float acc[8] = {};
    #pragma unroll
    for (int hh = 0; hh < H_DIM; hh++) {
        const int bh = b * 8 + hh;
        float il = g_il[(size_t)bh * T_DIM + q] * 0.125f;
        uint4 u = *((const uint4*)(g_p + ((size_t)bh * T_DIM + q) * T_DIM) + tid);
        __half2* hp = (__half2*)&u;
        #pragma unroll
        for (int c = 0; c < 4; c++) {
            float2 f = __half22float2(hp[c]);
            acc[c*2]   = fmaf(f.x, il, acc[c*2]);
            acc[c*2+1] = fmaf(f.y, il, acc[c*2+1]);
        }
    }
    float* dst = outAvg + ((size_t)b * T_DIM + q) * T_DIM + tid * 8;
    *(float4*)dst       = make_float4(acc[0], acc[1], acc[2], acc[3]);
    *(float4*)(dst + 4) = make_float4(acc[4], acc[5], acc[6], acc[7]);
}

// ---------------- launch ----------------
extern "C" void kernel_launch(void* const* d_in, const int* in_sizes, int n_in,
                              void* d_out, int out_size)
{
    const float* x     = (const float*)d_in[0];
    const float* w_in  = (const float*)d_in[1];
    const float* b_in  = (const float*)d_in[2];
    const float* w_out = (const float*)d_in[3];
    const float* b_out = (const float*)d_in[4];
    float* out = (float*)d_out;

    split_f32<<<(M_ROWS * E_DIM + 255) / 256, 256>>>(x, M_ROWS * E_DIM, 0);
    split_f32<<<(3 * E_DIM * E_DIM + 255) / 256, 256>>>(w_in, 3 * E_DIM * E_DIM, 1);
    split_f32<<<(E_DIM * E_DIM + 255) / 256, 256>>>(w_out, E_DIM * E_DIM, 2);

    cudaFuncSetAttribute(gemm_mma, cudaFuncAttributeMaxDynamicSharedMemorySize, 98304);
    gemm_mma<<<dim3(3 * E_DIM / 64, M_ROWS / 128), 256, 98304>>>(b_in, out, 0);

    cudaFuncSetAttribute(flash_mma, cudaFuncAttributeMaxDynamicSharedMemorySize, 98304);
    flash_mma<<<dim3(T_DIM / 128, BH), 128, 98304>>>();

    avg_sum<<<B_DIM * T_DIM, 256>>>(out + ATTN_ELEMS);

    gemm_mma<<<dim3(E_DIM / 64, M_ROWS / 128), 256, 98304>>>(b_out, out, 1);
}

// round 6
// speedup vs baseline: 4.7478x; 1.1494x over previous
#include <cuda_runtime.h>
#include <cuda_bf16.h>
#include <cuda_fp16.h>
#include <cstdint>
#include <math.h>

#define T_DIM 2048
#define B_DIM 4
#define E_DIM 512
#define H_DIM 8
#define HD    64
#define BH    (B_DIM*H_DIM)
#define SCALE 0.125f
#define M_ROWS (T_DIM*B_DIM)
#define ATTN_ELEMS (T_DIM*B_DIM*E_DIM)

// ---------------- scratch globals ----------------
__device__ __nv_bfloat16 g_xh[M_ROWS * E_DIM];
__device__ __nv_bfloat16 g_xl[M_ROWS * E_DIM];
__device__ __nv_bfloat16 g_wih[3 * E_DIM * E_DIM];
__device__ __nv_bfloat16 g_wil[3 * E_DIM * E_DIM];
__device__ __nv_bfloat16 g_woh[E_DIM * E_DIM];
__device__ __nv_bfloat16 g_wol[E_DIM * E_DIM];
__device__ __nv_bfloat16 g_qh[BH * T_DIM * HD];
__device__ __nv_bfloat16 g_ql[BH * T_DIM * HD];
__device__ __nv_bfloat16 g_kh[BH * T_DIM * HD];
__device__ __nv_bfloat16 g_kl[BH * T_DIM * HD];
__device__ __nv_bfloat16 g_vth[BH * HD * T_DIM];   // [bh][d][t]
__device__ __nv_bfloat16 g_vtl[BH * HD * T_DIM];
__device__ __nv_bfloat16 g_ch[M_ROWS * E_DIM];     // ctx hi  [t*B+b][e]
__device__ __nv_bfloat16 g_cl[M_ROWS * E_DIM];
__device__ float g_il[BH * T_DIM];
__device__ __align__(16) __half g_p[(size_t)BH * T_DIM * T_DIM];  // 256MB, exp(s) unnormalized

// ---------------- helpers ----------------
__device__ __forceinline__ uint32_t smem_u32(const void* p) {
    uint32_t a;
    asm("{ .reg .u64 t; cvta.to.shared.u64 t, %1; cvt.u32.u64 %0, t; }" : "=r"(a) : "l"(p));
    return a;
}

__device__ __forceinline__ void ldsm4(uint32_t addr, uint32_t* r) {
    asm volatile("ldmatrix.sync.aligned.m8n8.x4.shared.b16 {%0,%1,%2,%3}, [%4];"
                 : "=r"(r[0]), "=r"(r[1]), "=r"(r[2]), "=r"(r[3]) : "r"(addr));
}

__device__ __forceinline__ void mma_bf(float* c, const uint32_t* a, const uint32_t* b) {
    asm volatile("mma.sync.aligned.m16n8k16.row.col.f32.bf16.bf16.f32 "
                 "{%0,%1,%2,%3},{%4,%5,%6,%7},{%8,%9},{%0,%1,%2,%3};"
                 : "+f"(c[0]), "+f"(c[1]), "+f"(c[2]), "+f"(c[3])
                 : "r"(a[0]), "r"(a[1]), "r"(a[2]), "r"(a[3]), "r"(b[0]), "r"(b[1]));
}

__device__ __forceinline__ void cpa16(uint32_t dst, const void* src) {
    asm volatile("cp.async.cg.shared.global [%0], [%1], 16;" :: "r"(dst), "l"(src));
}
#define CP_COMMIT() asm volatile("cp.async.commit_group;" ::: "memory")
#define CP_WAIT1()  asm volatile("cp.async.wait_group 1;" ::: "memory")

// tiles: rows x 64 bf16, row pitch 128B, 16B-chunk XOR swizzle
__device__ __forceinline__ uint32_t addrA(uint32_t base, int m0, int kc, int lane) {
    int g = lane >> 3, r8 = lane & 7;
    int row = m0 + r8 + ((g & 1) << 3);
    int ch  = kc + (g >> 1);
    return base + row * 128 + ((ch ^ (row & 7)) << 4);
}
__device__ __forceinline__ uint32_t addrB(uint32_t base, int n0, int kc, int lane) {
    int g = lane >> 3, r8 = lane & 7;
    int row = n0 + r8 + ((g >> 1) << 3);
    int ch  = kc + (g & 1);
    return base + row * 128 + ((ch ^ (row & 7)) << 4);
}

// 32x32 warp tile step for projection GEMMs (3 split passes)
__device__ __forceinline__ void warp_step(float c[2][4][4],
    uint32_t AHb, uint32_t ALb, uint32_t BHb, uint32_t BLb,
    int wm0, int wn0, int kc, int lane)
{
    uint32_t ah[2][4], al[2][4], bhf[4][2], blf[4][2];
    #pragma unroll
    for (int i = 0; i < 2; i++) {
        ldsm4(addrA(AHb, wm0 + i * 16, kc, lane), ah[i]);
        ldsm4(addrA(ALb, wm0 + i * 16, kc, lane), al[i]);
    }
    #pragma unroll
    for (int jj = 0; jj < 2; jj++) {
        uint32_t t[4];
        ldsm4(addrB(BHb, wn0 + jj * 16, kc, lane), t);
        bhf[jj*2][0] = t[0]; bhf[jj*2][1] = t[1];
        bhf[jj*2+1][0] = t[2]; bhf[jj*2+1][1] = t[3];
        ldsm4(addrB(BLb, wn0 + jj * 16, kc, lane), t);
        blf[jj*2][0] = t[0]; blf[jj*2][1] = t[1];
        blf[jj*2+1][0] = t[2]; blf[jj*2+1][1] = t[3];
    }
    #pragma unroll
    for (int i = 0; i < 2; i++)
        #pragma unroll
        for (int j = 0; j < 4; j++) {
            mma_bf(c[i][j], ah[i], bhf[j]);
            mma_bf(c[i][j], ah[i], blf[j]);
            mma_bf(c[i][j], al[i], bhf[j]);
        }
}

// fast hi/lo pack: hi = rn-bf16x2 of (x,y); lo = exact residual, rn to bf16x2
__device__ __forceinline__ uint32_t packsplit2(float x, float y, uint32_t* lo) {
    __nv_bfloat162 h2 = __floats2bfloat162_rn(x, y);
    uint32_t hb = *(uint32_t*)&h2;
    float hx = __uint_as_float(hb << 16);
    float hy = __uint_as_float(hb & 0xffff0000u);
    __nv_bfloat162 l2 = __floats2bfloat162_rn(x - hx, y - hy);
    *lo = *(uint32_t*)&l2;
    return hb;
}

// ---------------- merged split kernel ----------------
#define NX  (M_ROWS * E_DIM)
#define NWI (3 * E_DIM * E_DIM)
#define NWO (E_DIM * E_DIM)
__global__ void split_all(const float* __restrict__ x,
                          const float* __restrict__ wi,
                          const float* __restrict__ wo)
{
    int i = blockIdx.x * blockDim.x + threadIdx.x;
    const float* src; __nv_bfloat16 *hi, *lo; int idx;
    if (i < NX)                { src = x;  hi = g_xh;  lo = g_xl;  idx = i; }
    else if (i < NX + NWI)     { src = wi; hi = g_wih; lo = g_wil; idx = i - NX; }
    else if (i < NX + NWI + NWO){ src = wo; hi = g_woh; lo = g_wol; idx = i - NX - NWI; }
    else return;
    float v = src[idx];
    __nv_bfloat16 h = __float2bfloat16(v);
    hi[idx] = h;
    lo[idx] = __float2bfloat16(v - __bfloat162float(h));
}

// ---------------- projection GEMM (cp.async double-buffered) ----------------
__device__ __forceinline__ void gemm_issue(uint32_t stage_base,
    const __nv_bfloat16* Ah, const __nv_bfloat16* Al,
    const __nv_bfloat16* Bh, const __nv_bfloat16* Bl,
    int m0, int n0, int ko, int tid)
{
    #pragma unroll
    for (int i = 0; i < 4; i++) {
        int idx = tid + i * 256;          // 0..1023
        int r = idx >> 3, ch = idx & 7;
        uint32_t off = r * 128 + ((ch ^ (r & 7)) << 4);
        cpa16(stage_base + off,         Ah + (size_t)(m0 + r) * E_DIM + ko + ch * 8);
        cpa16(stage_base + 16384 + off, Al + (size_t)(m0 + r) * E_DIM + ko + ch * 8);
    }
    #pragma unroll
    for (int i = 0; i < 2; i++) {
        int idx = tid + i * 256;          // 0..511
        int r = idx >> 3, ch = idx & 7;
        uint32_t off = r * 128 + ((ch ^ (r & 7)) << 4);
        cpa16(stage_base + 32768 + off, Bh + (size_t)(n0 + r) * E_DIM + ko + ch * 8);
        cpa16(stage_base + 40960 + off, Bl + (size_t)(n0 + r) * E_DIM + ko + ch * 8);
    }
}

__global__ __launch_bounds__(256) void gemm_mma(const float* __restrict__ bias,
                                                float* __restrict__ C, int mode)
{
    extern __shared__ char smem[];
    const __nv_bfloat16 *Ah, *Al, *Bh, *Bl;
    if (mode == 0) { Ah = g_xh; Al = g_xl; Bh = g_wih; Bl = g_wil; }
    else           { Ah = g_ch; Al = g_cl; Bh = g_woh; Bl = g_wol; }

    const uint32_t sb = smem_u32(smem);
    const int tid = threadIdx.x, lane = tid & 31, wid = tid >> 5;
    const int wm0 = (wid & 3) * 32, wn0 = (wid >> 2) * 32;
    const int m0 = blockIdx.y * 128, n0 = blockIdx.x * 64;

    gemm_issue(sb,         Ah, Al, Bh, Bl, m0, n0, 0,  tid); CP_COMMIT();
    gemm_issue(sb + 49152, Ah, Al, Bh, Bl, m0, n0, 64, tid); CP_COMMIT();

    float c[2][4][4] = {};
    for (int s = 0; s < 8; s++) {
        CP_WAIT1();
        __syncthreads();
        uint32_t st = sb + (s & 1) * 49152;
        #pragma unroll
        for (int kc = 0; kc < 8; kc += 2)
            warp_step(c, st, st + 16384, st + 32768, st + 40960, wm0, wn0, kc, lane);
        __syncthreads();
        if (s + 2 < 8)
            gemm_issue(sb + (s & 1) * 49152, Ah, Al, Bh, Bl, m0, n0, (s + 2) * 64, tid);
        CP_COMMIT();
    }

    #pragma unroll
    for (int i = 0; i < 2; i++)
        #pragma unroll
        for (int j = 0; j < 4; j++)
            #pragma unroll
            for (int e = 0; e < 4; e++) {
                int rg = m0 + wm0 + i * 16 + (lane >> 2) + ((e >> 1) << 3);
                int n  = n0 + wn0 + j * 8 + (lane & 3) * 2 + (e & 1);
                float v = c[i][j][e] + bias[n];
                if (mode == 0) {
                    int t = rg >> 2, bb = rg & 3;
                    int sect = n >> 9, jm = n & 511;
                    int hh = jm >> 6, d = jm & 63;
                    int bh = bb * 8 + hh;
                    if (sect == 2) {
                        size_t dst = ((size_t)bh * HD + d) * T_DIM + t;
                        __nv_bfloat16 h = __float2bfloat16(v);
                        g_vth[dst] = h;
                        g_vtl[dst] = __float2bfloat16(v - __bfloat162float(h));
                    } else {
                        size_t dst = ((size_t)bh * T_DIM + t) * HD + d;
                        if (sect == 0) {
                            v *= SCALE;
                            __nv_bfloat16 h = __float2bfloat16(v);
                            g_qh[dst] = h;
                            g_ql[dst] = __float2bfloat16(v - __bfloat162float(h));
                        } else {
                            __nv_bfloat16 h = __float2bfloat16(v);
                            g_kh[dst] = h;
                            g_kl[dst] = __float2bfloat16(v - __bfloat162float(h));
                        }
                    }
                } else {
                    C[(size_t)rg * E_DIM + n] = v;
                }
            }
}

// ---------------- flash attention: register-resident PV ----------------
// 128 threads (4 warps), q-tile 128 (32 rows/warp, full k width per warp).
// smem: QH 0, QL 16384, KVbuf0 32768, KVbuf1 65536
__device__ __forceinline__ void flash_issue_kv(uint32_t buf, int bh, int k0, int tid)
{
    #pragma unroll
    for (int i = 0; i < 4; i++) {
        int idx = tid + i * 128;          // 0..511
        int r = idx >> 3, ch = idx & 7;
        uint32_t off = r * 128 + ((ch ^ (r & 7)) << 4);
        const size_t kof = ((size_t)bh * T_DIM + k0 + r) * HD + ch * 8;
        const size_t vof = ((size_t)bh * HD + r) * T_DIM + k0 + ch * 8;
        cpa16(buf + off,         g_kh + kof);
        cpa16(buf + 8192 + off,  g_kl + kof);
        cpa16(buf + 16384 + off, g_vth + vof);
        cpa16(buf + 24576 + off, g_vtl + vof);
    }
}

__global__ __launch_bounds__(128, 2) void flash_mma()
{
    extern __shared__ char smem[];
    const uint32_t sb = smem_u32(smem);
    const int tid = threadIdx.x, lane = tid & 31, w = tid >> 5;
    const int bh = blockIdx.y, q0 = blockIdx.x * 128;
    const int b = bh >> 3, h = bh & 7;
    const int wq0 = w * 32;

    flash_issue_kv(sb + 32768, bh, 0, tid);  CP_COMMIT();
    flash_issue_kv(sb + 65536, bh, 64, tid); CP_COMMIT();

    {
        const __nv_bfloat16* Qh = g_qh + ((size_t)bh * T_DIM + q0) * HD;
        const __nv_bfloat16* Ql = g_ql + ((size_t)bh * T_DIM + q0) * HD;
        #pragma unroll
        for (int i = 0; i < 8; i++) {
            int idx = tid + i * 128;      // 0..1023
            int r = idx >> 3, ch = idx & 7;
            uint32_t off = r * 128 + ((ch ^ (r & 7)) << 4);
            *(uint4*)(smem + off)         = *(const uint4*)(Qh + (size_t)r * HD + ch * 8);
            *(uint4*)(smem + 16384 + off) = *(const uint4*)(Ql + (size_t)r * HD + ch * 8);
        }
    }
    __syncthreads();

    uint32_t qh[2][4][4], ql[2][4][4];
    #pragma unroll
    for (int i = 0; i < 2; i++)
        #pragma unroll
        for (int kk = 0; kk < 4; kk++) {
            ldsm4(addrA(sb,         wq0 + i * 16, 2 * kk, lane), qh[i][kk]);
            ldsm4(addrA(sb + 16384, wq0 + i * 16, 2 * kk, lane), ql[i][kk]);
        }

    float o[2][8][4] = {};
    float rs[4] = {};

    for (int kt = 0; kt < T_DIM / 64; kt++) {
        CP_WAIT1();
        __syncthreads();
        const uint32_t buf = sb + 32768 + (kt & 1) * 32768;

        // S = Q K^T  (32 x 64 per warp)
        float s[2][8][4] = {};
        #pragma unroll
        for (int kk = 0; kk < 4; kk++)
            #pragma unroll
            for (int jj = 0; jj < 4; jj++) {
                uint32_t th[4], tl[4];
                ldsm4(addrB(buf,        jj * 16, 2 * kk, lane), th);
                ldsm4(addrB(buf + 8192, jj * 16, 2 * kk, lane), tl);
                uint32_t bh0[2] = {th[0], th[1]}, bh1[2] = {th[2], th[3]};
                uint32_t bl0[2] = {tl[0], tl[1]}, bl1[2] = {tl[2], tl[3]};
                #pragma unroll
                for (int i = 0; i < 2; i++) {
                    mma_bf(s[i][jj*2], qh[i][kk], bh0);
                    mma_bf(s[i][jj*2], qh[i][kk], bl0);
                    mma_bf(s[i][jj*2], ql[i][kk], bh0);
                    mma_bf(s[i][jj*2+1], qh[i][kk], bh1);
                    mma_bf(s[i][jj*2+1], qh[i][kk], bl1);
                    mma_bf(s[i][jj*2+1], ql[i][kk], bh1);
                }
            }

        // exp (MUFU) + row sums + stream P to gmem
        #pragma unroll
        for (int i = 0; i < 2; i++)
            #pragma unroll
            for (int j = 0; j < 8; j++) {
                float p0 = __expf(s[i][j][0]), p1 = __expf(s[i][j][1]);
                float p2 = __expf(s[i][j][2]), p3 = __expf(s[i][j][3]);
                s[i][j][0] = p0; s[i][j][1] = p1; s[i][j][2] = p2; s[i][j][3] = p3;
                rs[i*2]   += p0 + p1;
                rs[i*2+1] += p2 + p3;
                int col = kt * 64 + j * 8 + (lane & 3) * 2;
                int r0 = q0 + wq0 + i * 16 + (lane >> 2);
                __half2* d0 = (__half2*)(g_p + ((size_t)bh * T_DIM + r0) * T_DIM + col);
                __half2* d1 = (__half2*)(g_p + ((size_t)bh * T_DIM + r0 + 8) * T_DIM + col);
                __stcs(d0, __floats2half2_rn(p0, p1));
                __stcs(d1, __floats2half2_rn(p2, p3));
            }

        // pack P into PV A-fragments (registers only)
        uint32_t aPh[2][4][4], aPl[2][4][4];
        #pragma unroll
        for (int i = 0; i < 2; i++)
            #pragma unroll
            for (int kk = 0; kk < 4; kk++) {
                aPh[i][kk][0] = packsplit2(s[i][2*kk][0],   s[i][2*kk][1],   &aPl[i][kk][0]);
                aPh[i][kk][1] = packsplit2(s[i][2*kk][2],   s[i][2*kk][3],   &aPl[i][kk][1]);
                aPh[i][kk][2] = packsplit2(s[i][2*kk+1][0], s[i][2*kk+1][1], &aPl[i][kk][2]);
                aPh[i][kk][3] = packsplit2(s[i][2*kk+1][2], s[i][2*kk+1][3], &aPl[i][kk][3]);
            }

        // O += P V  (B = Vt in smem)
        #pragma unroll
        for (int kk = 0; kk < 4; kk++)
            #pragma unroll
            for (int jj = 0; jj < 4; jj++) {
                uint32_t th[4], tl[4];
                ldsm4(addrB(buf + 16384, jj * 16, 2 * kk, lane), th);
                ldsm4(addrB(buf + 24576, jj * 16, 2 * kk, lane), tl);
                uint32_t bh0[2] = {th[0], th[1]}, bh1[2] = {th[2], th[3]};
                uint32_t bl0[2] = {tl[0], tl[1]}, bl1[2] = {tl[2], tl[3]};
                #pragma unroll
                for (int i = 0; i < 2; i++) {
                    mma_bf(o[i][jj*2], aPh[i][kk], bh0);
                    mma_bf(o[i][jj*2], aPh[i][kk], bl0);
                    mma_bf(o[i][jj*2], aPl[i][kk], bh0);
                    mma_bf(o[i][jj*2+1], aPh[i][kk], bh1);
                    mma_bf(o[i][jj*2+1], aPh[i][kk], bl1);
                    mma_bf(o[i][jj*2+1], aPl[i][kk], bh1);
                }
            }
        __syncthreads();
        if (kt + 2 < T_DIM / 64)
            flash_issue_kv(sb + 32768 + (kt & 1) * 32768, bh, (kt + 2) * 64, tid);
        CP_COMMIT();
    }

    #pragma unroll
    for (int x = 0; x < 4; x++) {
        rs[x] += __shfl_xor_sync(0xffffffffu, rs[x], 1);
        rs[x] += __shfl_xor_sync(0xffffffffu, rs[x], 2);
    }
    float il[4] = {1.0f / rs[0], 1.0f / rs[1], 1.0f / rs[2], 1.0f / rs[3]};

    #pragma unroll
    for (int i = 0; i < 2; i++)
        #pragma unroll
        for (int hf = 0; hf < 2; hf++) {
            int r = wq0 + i * 16 + (lane >> 2) + hf * 8;
            float s_il = il[i*2 + hf];
            #pragma unroll
            for (int j = 0; j < 8; j++) {
                int cc = j * 8 + (lane & 3) * 2;
                uint32_t lo;
                uint32_t hi = packsplit2(o[i][j][hf*2] * s_il, o[i][j][hf*2+1] * s_il, &lo);
                size_t off = ((size_t)(q0 + r) * B_DIM + b) * E_DIM + h * HD + cc;
                *(uint32_t*)&g_ch[off] = hi;
                *(uint32_t*)&g_cl[off] = lo;
            }
            if ((lane & 3) == 0)
                g_il[(size_t)bh * T_DIM + q0 + r] = s_il;
        }
}

// ---------------- avg_weights: pure memory pass over stored P ----------------
__global__ __launch_bounds__(256) void avg_sum(float* __restrict__ outAvg)
{
    const int blk = blockIdx.x;           // b*T + q
    const int b = blk >> 11, q = blk & 2047;
    const int tid = threadIdx.x;

    float acc[8] = {};
    #pragma unroll
    for (int hh = 0; hh < H_DIM; hh++) {
        const int bh = b * 8 + hh;
        float il = g_il[(size_t)bh * T_DIM + q] * 0.125f;
        uint4 u = *((const uint4*)(g_p + ((size_t)bh * T_DIM + q) * T_DIM) + tid);
        __half2* hp = (__half2*)&u;
        #pragma unroll
        for (int c = 0; c < 4; c++) {
            float2 f = __half22float2(hp[c]);
            acc[c*2]   = fmaf(f.x, il, acc[c*2]);
            acc[c*2+1] = fmaf(f.y, il, acc[c*2+1]);
        }
    }
    float* dst = outAvg + ((size_t)b * T_DIM + q) * T_DIM + tid * 8;
    *(float4*)dst       = make_float4(acc[0], acc[1], acc[2], acc[3]);
    *(float4*)(dst + 4) = make_float4(acc[4], acc[5], acc[6], acc[7]);
}

// ---------------- launch ----------------
extern "C" void kernel_launch(void* const* d_in, const int* in_sizes, int n_in,
                              void* d_out, int out_size)
{
    const float* x     = (const float*)d_in[0];
    const float* w_in  = (const float*)d_in[1];
    const float* b_in  = (const float*)d_in[2];
    const float* w_out = (const float*)d_in[3];
    const float* b_out = (const float*)d_in[4];
    float* out = (float*)d_out;

    static cudaStream_t s2 = nullptr;
    static cudaEvent_t ev1 = nullptr, ev2 = nullptr;
    if (!s2) {
        cudaStreamCreateWithFlags(&s2, cudaStreamNonBlocking);
        cudaEventCreateWithFlags(&ev1, cudaEventDisableTiming);
        cudaEventCreateWithFlags(&ev2, cudaEventDisableTiming);
    }

    split_all<<<(NX + NWI + NWO + 255) / 256, 256>>>(x, w_in, w_out);

    cudaFuncSetAttribute(gemm_mma, cudaFuncAttributeMaxDynamicSharedMemorySize, 98304);
    gemm_mma<<<dim3(3 * E_DIM / 64, M_ROWS / 128), 256, 98304>>>(b_in, out, 0);

    cudaFuncSetAttribute(flash_mma, cudaFuncAttributeMaxDynamicSharedMemorySize, 98304);
    flash_mma<<<dim3(T_DIM / 128, BH), 128, 98304>>>();

    // fork: avg_sum (DRAM-bound) runs concurrently with out-proj gemm (tensor-bound)
    cudaEventRecord(ev1, 0);
    cudaStreamWaitEvent(s2, ev1, 0);
    avg_sum<<<B_DIM * T_DIM, 256, 0, s2>>>(out + ATTN_ELEMS);
    cudaEventRecord(ev2, s2);

    gemm_mma<<<dim3(E_DIM / 64, M_ROWS / 128), 256, 98304>>>(b_out, out, 1);

    cudaStreamWaitEvent(0, ev2, 0);
}